// round 2
// baseline (speedup 1.0000x reference)
#include <cuda_runtime.h>
#include <cstdint>

#define VOCAB 30522
#define ROWL  (2*VOCAB)          // 61044 floats per W row
#define KDIM  2048
#define TOPKN 32
#define NOUT  18
#define BATCH 256
#define SEQ   128
#define KC    8                  // k-rows per block
#define CW    1024               // columns per chunk
#define NCH   ((VOCAB + CW - 1) / CW)   // 30 chunks over the lower half

// ---------------- global scratch (no allocations allowed) ----------------
__device__ float g_acts[BATCH * KDIM];            // 2 MB
__device__ int   g_sorted[BATCH * SEQ];           // sorted nonzero ids (sentinel 0x7FFFFFFF)
__device__ int   g_pstart[BATCH * (NCH + 1)];     // per-batch chunk start offsets

// ---------------- kernel 1: per-batch rank sort + chunk offsets ----------------
__global__ void k_sort(const int* __restrict__ ids) {
    __shared__ int s[SEQ];    // keys for ranking
    __shared__ int s2[SEQ];   // sorted keys
    const int b = blockIdx.x;
    const int t = threadIdx.x;                 // 128 threads

    const int id  = ids[b * SEQ + t];
    const int key = (id == 0) ? 0x7FFFFFFF : id;   // mask: id==0 contributes nothing
    s[t] = key;
    __syncthreads();

    int rank = 0;
    #pragma unroll 16
    for (int j = 0; j < SEQ; j++) {
        const int kj = s[j];
        rank += (kj < key) || (kj == key && j < t);   // unique ranks (stable)
    }
    s2[rank] = key;
    __syncthreads();

    g_sorted[b * SEQ + t] = s2[t];

    // chunk boundaries: pstart[ch] = #keys < ch*CW  (sentinels never counted)
    if (t <= NCH) {
        const int target = t * CW;
        int lo = 0, hi = SEQ;
        while (lo < hi) {
            const int m = (lo + hi) >> 1;
            if (s2[m] < target) lo = m + 1; else hi = m;
        }
        g_pstart[b * (NCH + 1) + t] = lo;
    }
}

// ---------------- kernel 2: stream W rows, sparse accumulate ----------------
// block = 256 threads (thread t <-> batch t), grid = KDIM/KC = 256 blocks.
// smem chunk sm[j][cc] = W[k0+j][c0+cc] + W[k0+j][c0+cc+VOCAB]  (halves pre-folded)
__global__ __launch_bounds__(256, 2) void k_spmm(const float* __restrict__ W) {
    __shared__ float sm[KC * CW];   // 32 KB
    const int k0 = blockIdx.x * KC;
    const int b  = threadIdx.x;

    float acc[KC];
    #pragma unroll
    for (int j = 0; j < KC; j++) acc[j] = 0.f;

    const int* __restrict__ myids = g_sorted + b * SEQ;
    const int* __restrict__ pst   = g_pstart + b * (NCH + 1);
    int p = 0;

    // per-thread slice of a chunk: thread b owns float4 at column c0 + 4b of each row
    float4 lo[KC];
    float2 up0[KC], up1[KC];

    // prefetch chunk 0 (always full: 4b+3 <= 1023 < VOCAB)
    {
        const int col = 4 * b;
        #pragma unroll
        for (int j = 0; j < KC; j++) {
            const float* row = W + (size_t)(k0 + j) * ROWL;
            lo[j]  = __ldg(reinterpret_cast<const float4*>(row + col));
            up0[j] = __ldg(reinterpret_cast<const float2*>(row + col + VOCAB));
            up1[j] = __ldg(reinterpret_cast<const float2*>(row + col + VOCAB + 2));
        }
    }

    for (int ch = 0; ch < NCH; ch++) {
        const int c0 = ch * CW;
        __syncthreads();                       // previous consume done, smem free
        #pragma unroll
        for (int j = 0; j < KC; j++) {         // fold halves, store chunk
            float4 v;
            v.x = lo[j].x + up0[j].x;
            v.y = lo[j].y + up0[j].y;
            v.z = lo[j].z + up1[j].x;
            v.w = lo[j].w + up1[j].y;
            *reinterpret_cast<float4*>(&sm[j * CW + 4 * b]) = v;
        }
        __syncthreads();

        // issue next chunk's loads NOW (in flight during consume)
        if (ch + 1 < NCH) {
            const int col = (ch + 1) * CW + 4 * b;
            if (col + 3 < VOCAB) {             // fast path (all chunks but the last)
                #pragma unroll
                for (int j = 0; j < KC; j++) {
                    const float* row = W + (size_t)(k0 + j) * ROWL;
                    lo[j]  = __ldg(reinterpret_cast<const float4*>(row + col));
                    up0[j] = __ldg(reinterpret_cast<const float2*>(row + col + VOCAB));
                    up1[j] = __ldg(reinterpret_cast<const float2*>(row + col + VOCAB + 2));
                }
            } else {                           // tail: scalar guarded, pre-folded into lo
                #pragma unroll
                for (int j = 0; j < KC; j++) {
                    const float* row = W + (size_t)(k0 + j) * ROWL;
                    float v[4];
                    #pragma unroll
                    for (int x = 0; x < 4; x++) {
                        const int c = col + x;
                        v[x] = (c < VOCAB) ? (row[c] + row[c + VOCAB]) : 0.f;
                    }
                    lo[j]  = make_float4(v[0], v[1], v[2], v[3]);
                    up0[j] = make_float2(0.f, 0.f);
                    up1[j] = make_float2(0.f, 0.f);
                }
            }
        }

        // consume: known trip count -> independent id loads (MLP), no pointer chase
        const int pend = pst[ch + 1];
        for (; p < pend; ++p) {
            const int cc = myids[p] - c0;
            #pragma unroll
            for (int j = 0; j < KC; j++) acc[j] += sm[j * CW + cc];
        }
    }

    #pragma unroll
    for (int j = 0; j < KC; j++)
        g_acts[(size_t)b * KDIM + k0 + j] = acc[j];
}

// ---------------- kernel 3: exact fp32 top-32 + logits ----------------
__global__ void k_topk(const float* __restrict__ Wa, const float* __restrict__ ba,
                       float* __restrict__ out) {
    __shared__ float rv[8];
    __shared__ int   ri[8];
    __shared__ int   s_sel[TOPKN];
    __shared__ int   s_idx;
    const int b = blockIdx.x;
    const int t = threadIdx.x;                 // 256 threads
    const int lane = t & 31, wid = t >> 5;

    float v[8];
    #pragma unroll
    for (int i = 0; i < 8; i++) v[i] = g_acts[(size_t)b * KDIM + t + i * 256];

    for (int it = 0; it < TOPKN; it++) {
        float bv = v[0]; int bi = t;
        #pragma unroll
        for (int i = 1; i < 8; i++) {
            const int idx = t + i * 256;
            if (v[i] > bv || (v[i] == bv && idx < bi)) { bv = v[i]; bi = idx; }
        }
        #pragma unroll
        for (int o = 16; o > 0; o >>= 1) {     // warp argmax, jax tie-break (lower idx)
            const float ov = __shfl_down_sync(0xffffffff, bv, o);
            const int   oi = __shfl_down_sync(0xffffffff, bi, o);
            if (ov > bv || (ov == bv && oi < bi)) { bv = ov; bi = oi; }
        }
        if (lane == 0) { rv[wid] = bv; ri[wid] = bi; }
        __syncthreads();
        if (t == 0) {
            float mv = rv[0]; int mi = ri[0];
            #pragma unroll
            for (int w = 1; w < 8; w++)
                if (rv[w] > mv || (rv[w] == mv && ri[w] < mi)) { mv = rv[w]; mi = ri[w]; }
            s_idx = mi; s_sel[it] = mi;
        }
        __syncthreads();
        const int mi = s_idx;
        if ((mi & 255) == t) v[mi >> 8] = -3.402823466e38f;   // remove selected
    }
    __syncthreads();

    if (t < NOUT) {
        float s = ba[t];
        #pragma unroll
        for (int i = 0; i < TOPKN; i++) s += Wa[(size_t)t * KDIM + s_sel[i]];
        out[(size_t)b * NOUT + t] = s;
    }
}

// ---------------- launch ----------------
extern "C" void kernel_launch(void* const* d_in, const int* in_sizes, int n_in,
                              void* d_out, int out_size) {
    const int*   ids = (const int*)d_in[0];
    const float* W   = (const float*)d_in[1];
    const float* Wa  = (const float*)d_in[2];
    const float* ba  = (const float*)d_in[3];
    float*       out = (float*)d_out;

    k_sort<<<BATCH, SEQ>>>(ids);
    k_spmm<<<KDIM / KC, BATCH>>>(W);
    k_topk<<<BATCH, BATCH>>>(Wa, ba, out);
}